// round 6
// baseline (speedup 1.0000x reference)
#include <cuda_runtime.h>

#define NN 4
#define HH 480
#define WW 640

// Scratch (static device arrays; no allocation anywhere). All NHWC float4.
__device__ float4 g_b1[NN * HH * WW];   // ping
__device__ float4 g_b2[NN * HH * WW];   // pong / theta
__device__ float4 g_xt[NN * HH * WW];   // x packed NHWC (c=0..2, lane w = 0)

// ---------------------------------------------------------------------------
// Kernel 0: pack x [N,3,H,W] -> NHWC float4 (4th lane zero)
// ---------------------------------------------------------------------------
__global__ void __launch_bounds__(256) pack_x_kernel(const float* __restrict__ x) {
    int idx = blockIdx.x * 256 + threadIdx.x;
    const int total = NN * HH * WW;
    if (idx >= total) return;
    int n  = idx / (HH * WW);
    int hw = idx - n * (HH * WW);
    const float* xb = x + (size_t)n * 3 * HH * WW + hw;
    float4 v;
    v.x = __ldg(&xb[0]);
    v.y = __ldg(&xb[HH * WW]);
    v.z = __ldg(&xb[2 * HH * WW]);
    v.w = 0.f;
    g_xt[idx] = v;
}

// ---------------------------------------------------------------------------
// 5x5 conv, pad 2, NHWC float4 in/out (channels in lanes -> no ic loop).
// Block 32x8. Thread computes 4 ADJACENT px (x = x0 + 4*tx + 0..3) on TWO
// rows (y0+ty and y0+ty+8) -> tile covers 128x16 outputs; the 20 broadcast
// weight LDS.128 per ky are amortized over 8 pixels.
// SRC: 0 = g_xt, 1 = g_b1, 2 = g_b2.  DST: 1 = g_b1, 2 = g_b2.
// ---------------------------------------------------------------------------
template <int IC, int SRC, int DST>
__global__ void __launch_bounds__(256) conv5_kernel(
    const float* __restrict__ w, const float* __restrict__ b)
{
    __shared__ float4 tile4[20][132];   // rows y0-2 .. y0+17, cols x0-2 .. x0+129
    __shared__ float4 wsh[5][5][4];     // [ky][kx][oc] -> lanes = ic 0..3
    __shared__ float4 b4s;

    const int tx  = threadIdx.x;
    const int ty  = threadIdx.y;
    const int tid = ty * 32 + tx;
    const int x0  = blockIdx.x * 128;
    const int y0  = blockIdx.y * 16;
    const int n   = blockIdx.z;

    const float4* in = (SRC == 0) ? g_xt : (SRC == 1) ? g_b1 : g_b2;
    float4* out      = (DST == 1) ? g_b1 : g_b2;

    // weights: src layout [OC=4][IC][5][5] -> wsh[ky][kx][oc] lanes over ic
    if (tid < 100) {
        int oc = tid / 25;
        int k  = tid - oc * 25;        // ky*5+kx
        float4 wv;
        wv.x = __ldg(&w[(oc * IC + 0) * 25 + k]);
        wv.y = __ldg(&w[(oc * IC + 1) * 25 + k]);
        wv.z = __ldg(&w[(oc * IC + 2) * 25 + k]);
        wv.w = (IC == 4) ? __ldg(&w[(oc * IC + 3) * 25 + k]) : 0.f;
        wsh[k / 5][k % 5][oc] = wv;
    }
    if (tid == 0)
        b4s = make_float4(__ldg(&b[0]), __ldg(&b[1]), __ldg(&b[2]), __ldg(&b[3]));

    // input tile with halo (20 x 132 float4)
    const float4* inb = in + (size_t)n * HH * WW;
    for (int i = tid; i < 20 * 132; i += 256) {
        int r  = i / 132;
        int c  = i - r * 132;
        int gy = y0 + r - 2;
        int gx = x0 + c - 2;
        float4 v = make_float4(0.f, 0.f, 0.f, 0.f);
        if (gy >= 0 && gy < HH && gx >= 0 && gx < WW)
            v = __ldg(&inb[gy * WW + gx]);
        tile4[r][c] = v;
    }
    __syncthreads();

    float4 accA[4], accB[4];
#pragma unroll
    for (int p = 0; p < 4; ++p) { accA[p] = b4s; accB[p] = b4s; }

#pragma unroll 1
    for (int ky = 0; ky < 5; ++ky) {
        const float4* rowA = &tile4[ty + ky][4 * tx];
        const float4* rowB = &tile4[ty + 8 + ky][4 * tx];
        float4 vA[8], vB[8];
#pragma unroll
        for (int j = 0; j < 8; ++j) { vA[j] = rowA[j]; vB[j] = rowB[j]; }
#pragma unroll
        for (int kx = 0; kx < 5; ++kx) {
            const float4 w0 = wsh[ky][kx][0];
            const float4 w1 = wsh[ky][kx][1];
            const float4 w2 = wsh[ky][kx][2];
            const float4 w3 = wsh[ky][kx][3];
#pragma unroll
            for (int p = 0; p < 4; ++p) {
                const float4 a = vA[p + kx];
                accA[p].x += a.x * w0.x + a.y * w0.y + a.z * w0.z + a.w * w0.w;
                accA[p].y += a.x * w1.x + a.y * w1.y + a.z * w1.z + a.w * w1.w;
                accA[p].z += a.x * w2.x + a.y * w2.y + a.z * w2.z + a.w * w2.w;
                accA[p].w += a.x * w3.x + a.y * w3.y + a.z * w3.z + a.w * w3.w;
                const float4 c = vB[p + kx];
                accB[p].x += c.x * w0.x + c.y * w0.y + c.z * w0.z + c.w * w0.w;
                accB[p].y += c.x * w1.x + c.y * w1.y + c.z * w1.z + c.w * w1.w;
                accB[p].z += c.x * w2.x + c.y * w2.y + c.z * w2.z + c.w * w2.w;
                accB[p].w += c.x * w3.x + c.y * w3.y + c.z * w3.z + c.w * w3.w;
            }
        }
    }

    const int xb = x0 + 4 * tx;
    float4* oA = out + (size_t)n * HH * WW + (y0 + ty) * WW + xb;
    float4* oB = out + (size_t)n * HH * WW + (y0 + ty + 8) * WW + xb;
#pragma unroll
    for (int p = 0; p < 4; ++p) { oA[p] = accA[p]; oB[p] = accB[p]; }
}

// ---------------------------------------------------------------------------
// Fused: grid build + bilinear grid_sample + stride-3 3x3 conv epilogue.
// theta in NHWC float4 (g_b2). x in NHWC float4 (g_xt).
// Thread map: tx -> h (gathers coalesced along x columns), ty -> w.
// ---------------------------------------------------------------------------
__device__ __forceinline__ float4 fetch4(const float4* __restrict__ b, int x, int y) {
    if ((unsigned)x < (unsigned)WW && (unsigned)y < (unsigned)HH)
        return __ldg(&b[y * WW + x]);
    return make_float4(0.f, 0.f, 0.f, 0.f);
}

__global__ void __launch_bounds__(256) stn_sample_kernel(
    const float* __restrict__ wr, const float* __restrict__ br,
    float* __restrict__ out)
{
    __shared__ float wsh[81];
    __shared__ float bsh[3];
    __shared__ float so[3][32][9];

    const int tx  = threadIdx.x;
    const int ty  = threadIdx.y;
    const int tid = ty * 32 + tx;
    if (tid < 81) wsh[tid] = __ldg(&wr[tid]);
    if (tid < 3)  bsh[tid] = __ldg(&br[tid]);
    __syncthreads();

    const int h0 = blockIdx.x * 32;
    const int w0 = blockIdx.y * 8;
    const int n  = blockIdx.z;
    const int h  = h0 + tx;
    const int w  = w0 + ty;

    const float4* tb = g_b2 + (size_t)n * HH * WW;
    const float4* xb = g_xt + (size_t)n * HH * WW;

    const float4 th = __ldg(&tb[h * WW + w]);

    const float yy = -1.f + 2.f * (float)h / (float)(HH - 1);
    const float xx = -1.f + 2.f * (float)w / (float)(WW - 1);

    float acc0 = 0.f, acc1 = 0.f, acc2 = 0.f;

#pragma unroll
    for (int i = 0; i < 3; ++i) {
        const float lyv = (float)(i - 1) * (3.0f / (float)HH);
#pragma unroll
        for (int j = 0; j < 3; ++j) {
            const float lxv = (float)(j - 1) * (3.0f / (float)WW);
            const float gx = yy + th.x * lyv + th.y * lxv;   // grid[...,0] (x coord)
            const float gy = xx + th.z * lyv + th.w * lxv;   // grid[...,1] (y coord)
            const float ix = ((gx + 1.0f) * (float)WW - 1.0f) * 0.5f;
            const float iy = ((gy + 1.0f) * (float)HH - 1.0f) * 0.5f;
            const float ix0 = floorf(ix);
            const float iy0 = floorf(iy);
            const float wx1 = ix - ix0;
            const float wy1 = iy - iy0;
            const float wx0 = 1.0f - wx1;
            const float wy0 = 1.0f - wy1;
            const int xi = (int)ix0;
            const int yi = (int)iy0;

            const float4 v00 = fetch4(xb, xi,     yi);
            const float4 v10 = fetch4(xb, xi + 1, yi);
            const float4 v01 = fetch4(xb, xi,     yi + 1);
            const float4 v11 = fetch4(xb, xi + 1, yi + 1);

            const float w00 = wx0 * wy0, w10 = wx1 * wy0;
            const float w01 = wx0 * wy1, w11 = wx1 * wy1;

            const float vx = v00.x * w00 + v10.x * w10 + v01.x * w01 + v11.x * w11;
            const float vy = v00.y * w00 + v10.y * w10 + v01.y * w01 + v11.y * w11;
            const float vz = v00.z * w00 + v10.z * w10 + v01.z * w01 + v11.z * w11;

            const int k = i * 3 + j;
            acc0 += wsh[0 * 27 + k] * vx + wsh[0 * 27 + 9 + k] * vy + wsh[0 * 27 + 18 + k] * vz;
            acc1 += wsh[1 * 27 + k] * vx + wsh[1 * 27 + 9 + k] * vy + wsh[1 * 27 + 18 + k] * vz;
            acc2 += wsh[2 * 27 + k] * vx + wsh[2 * 27 + 9 + k] * vy + wsh[2 * 27 + 18 + k] * vz;
        }
    }

    so[0][tx][ty] = acc0 + bsh[0];
    so[1][tx][ty] = acc1 + bsh[1];
    so[2][tx][ty] = acc2 + bsh[2];
    __syncthreads();

    for (int e = tid; e < 3 * 32 * 8; e += 256) {
        int oc = e >> 8;
        int r  = (e >> 3) & 31;
        int c  = e & 7;
        out[((size_t)(n * 3 + oc) * HH + h0 + r) * WW + w0 + c] = so[oc][r][c];
    }
}

// ---------------------------------------------------------------------------
extern "C" void kernel_launch(void* const* d_in, const int* in_sizes, int n_in,
                              void* d_out, int out_size)
{
    const float* x  = (const float*)d_in[0];
    const float* w1 = (const float*)d_in[1];
    const float* b1 = (const float*)d_in[2];
    const float* w2 = (const float*)d_in[3];
    const float* b2 = (const float*)d_in[4];
    const float* w3 = (const float*)d_in[5];
    const float* b3 = (const float*)d_in[6];
    const float* w4 = (const float*)d_in[7];
    const float* b4 = (const float*)d_in[8];
    const float* wr = (const float*)d_in[9];
    const float* br = (const float*)d_in[10];
    float* out = (float*)d_out;

    const dim3 cb(32, 8);
    const dim3 cg(WW / 128, HH / 16, NN);    // (5, 30, 4)

    pack_x_kernel<<<(NN * HH * WW + 255) / 256, 256>>>(x);

    conv5_kernel<3, 0, 1><<<cg, cb>>>(w1, b1);   // xt -> b1
    conv5_kernel<4, 1, 2><<<cg, cb>>>(w2, b2);   // b1 -> b2
    conv5_kernel<4, 2, 1><<<cg, cb>>>(w3, b3);   // b2 -> b1
    conv5_kernel<4, 1, 2><<<cg, cb>>>(w4, b4);   // b1 -> b2 (theta NHWC4)

    const dim3 sb(32, 8);
    const dim3 sg(HH / 32, WW / 8, NN);      // (15, 80, 4)
    stn_sample_kernel<<<sg, sb>>>(wr, br, out);
}

// round 8
// speedup vs baseline: 1.5525x; 1.5525x over previous
#include <cuda_runtime.h>

#define NN 4
#define HH 480
#define WW 640
#define W4 (WW / 4)

// Scratch (static device arrays; no allocation anywhere)
__device__ float  g_t1[NN * 4 * HH * WW];   // ping (CHW)
__device__ float  g_t2[NN * 4 * HH * WW];   // pong / theta NHWC4
__device__ float4 g_xt[NN * HH * WW];       // x packed NHWC (c=0..2, lane w = 0)

// ---------------------------------------------------------------------------
// Kernel 0: pack x [N,3,H,W] -> NHWC float4 (4th lane zero)
// ---------------------------------------------------------------------------
__global__ void __launch_bounds__(256) pack_x_kernel(const float* __restrict__ x) {
    int idx = blockIdx.x * 256 + threadIdx.x;
    const int total = NN * HH * WW;
    if (idx >= total) return;
    int n  = idx / (HH * WW);
    int hw = idx - n * (HH * WW);
    const float* xb = x + (size_t)n * 3 * HH * WW + hw;
    float4 v;
    v.x = __ldg(&xb[0]);
    v.y = __ldg(&xb[HH * WW]);
    v.z = __ldg(&xb[2 * HH * WW]);
    v.w = 0.f;
    g_xt[idx] = v;
}

// ---------------------------------------------------------------------------
// 5x5 conv, pad 2, OC=4, CHW. Block 32x8; thread computes 4 ADJACENT px
// (x = x0 + 4*tx + 0..3) -> tile covers 128x8 outputs.
// Tile [IC][12][136] floats, origin (y0-2, x0-4): float4-aligned everywhere,
// prologue = 34 aligned LDG.128/STS.128 per (ic,row) (W%4==0 -> no partial f4).
// Row read = 3 LDS.128 (v[0..11], use v[2..10]).
// Weights float4 over oc per [ic][ky][kx] -> 5 broadcast LDS.128 per row.
// SRC: 0 = external x, 1 = g_t1, 2 = g_t2.  NHWC_OUT -> float4 theta out.
// ---------------------------------------------------------------------------
template <int IC, int SRC, int DST, bool NHWC_OUT>
__global__ void __launch_bounds__(256) conv5_kernel(
    const float* __restrict__ xin, const float* __restrict__ w,
    const float* __restrict__ b)
{
    __shared__ float  tile[IC][12][136];
    __shared__ float4 w4[IC][5][5];     // [ic][ky][kx] -> (oc0,oc1,oc2,oc3)
    __shared__ float4 b4s;

    const int tx  = threadIdx.x;
    const int ty  = threadIdx.y;
    const int tid = ty * 32 + tx;
    const int x0  = blockIdx.x * 128;
    const int y0  = blockIdx.y * 8;
    const int n   = blockIdx.z;

    const float* in = (SRC == 0) ? xin : (SRC == 1) ? g_t1 : g_t2;
    float* out      = (DST == 1) ? g_t1 : g_t2;

    // weights: src layout [OC=4][IC][5][5]
    if (tid < IC * 25) {
        int ic = tid / 25;
        int k  = tid - ic * 25;        // ky*5+kx
        w4[ic][k / 5][k % 5] = make_float4(
            __ldg(&w[(0 * IC + ic) * 25 + k]),
            __ldg(&w[(1 * IC + ic) * 25 + k]),
            __ldg(&w[(2 * IC + ic) * 25 + k]),
            __ldg(&w[(3 * IC + ic) * 25 + k]));
    }
    if (tid == 0)
        b4s = make_float4(__ldg(&b[0]), __ldg(&b[1]), __ldg(&b[2]), __ldg(&b[3]));

    // prologue: float4 tile loads. rows y0-2..y0+9, f4-cols x0/4-1 .. x0/4+32
    {
        const float4* in4 = reinterpret_cast<const float4*>(in + (size_t)n * IC * HH * WW);
        const int cbase = (x0 >> 2) - 1;
#pragma unroll 1
        for (int i = tid; i < IC * 12 * 34; i += 256) {
            int ic  = i / (12 * 34);
            int rem = i - ic * (12 * 34);
            int r   = rem / 34;
            int c4  = rem - r * 34;
            int gy  = y0 + r - 2;
            int gx4 = cbase + c4;
            float4 v = make_float4(0.f, 0.f, 0.f, 0.f);
            if ((unsigned)gy < (unsigned)HH && (unsigned)gx4 < (unsigned)W4)
                v = __ldg(&in4[((size_t)ic * HH + gy) * W4 + gx4]);
            *reinterpret_cast<float4*>(&tile[ic][r][4 * c4]) = v;
        }
    }
    __syncthreads();

    // acc[oc][px]
    float acc[4][4];
    {
        const float4 bb = b4s;
#pragma unroll
        for (int p = 0; p < 4; ++p) {
            acc[0][p] = bb.x; acc[1][p] = bb.y;
            acc[2][p] = bb.z; acc[3][p] = bb.w;
        }
    }

#pragma unroll 1
    for (int ic = 0; ic < IC; ++ic) {
#pragma unroll
        for (int ky = 0; ky < 5; ++ky) {
            const float4* rowp =
                reinterpret_cast<const float4*>(&tile[ic][ty + ky][4 * tx]);
            const float4 a0 = rowp[0];
            const float4 a1 = rowp[1];
            const float4 a2 = rowp[2];
            const float v[12] = {a0.x, a0.y, a0.z, a0.w,
                                 a1.x, a1.y, a1.z, a1.w,
                                 a2.x, a2.y, a2.z, a2.w};
#pragma unroll
            for (int kx = 0; kx < 5; ++kx) {
                const float4 wv = w4[ic][ky][kx];
#pragma unroll
                for (int p = 0; p < 4; ++p) {
                    const float x = v[2 + p + kx];
                    acc[0][p] += x * wv.x;
                    acc[1][p] += x * wv.y;
                    acc[2][p] += x * wv.z;
                    acc[3][p] += x * wv.w;
                }
            }
        }
    }

    const int y  = y0 + ty;
    const int xb = x0 + 4 * tx;

    if (NHWC_OUT) {
        float4* o4 = reinterpret_cast<float4*>(out) + (size_t)n * HH * WW + y * WW + xb;
#pragma unroll
        for (int p = 0; p < 4; ++p)
            o4[p] = make_float4(acc[0][p], acc[1][p], acc[2][p], acc[3][p]);
    } else {
#pragma unroll
        for (int oc = 0; oc < 4; ++oc) {
            float4* op = reinterpret_cast<float4*>(
                out + ((size_t)(n * 4 + oc) * HH + y) * WW + xb);
            *op = make_float4(acc[oc][0], acc[oc][1], acc[oc][2], acc[oc][3]);
        }
    }
}

// ---------------------------------------------------------------------------
// Fused: grid build + bilinear grid_sample + stride-3 3x3 conv epilogue.
// theta in NHWC float4 (g_t2). x in NHWC float4 (g_xt).
// Thread map: tx -> h (gathers coalesced along x columns), ty -> w.
// ---------------------------------------------------------------------------
__device__ __forceinline__ float4 fetch4(const float4* __restrict__ b, int x, int y) {
    if ((unsigned)x < (unsigned)WW && (unsigned)y < (unsigned)HH)
        return __ldg(&b[y * WW + x]);
    return make_float4(0.f, 0.f, 0.f, 0.f);
}

__global__ void __launch_bounds__(256) stn_sample_kernel(
    const float* __restrict__ wr, const float* __restrict__ br,
    float* __restrict__ out)
{
    __shared__ float wsh[81];
    __shared__ float bsh[3];
    __shared__ float so[3][32][9];

    const int tx  = threadIdx.x;
    const int ty  = threadIdx.y;
    const int tid = ty * 32 + tx;
    if (tid < 81) wsh[tid] = __ldg(&wr[tid]);
    if (tid < 3)  bsh[tid] = __ldg(&br[tid]);
    __syncthreads();

    const int h0 = blockIdx.x * 32;
    const int w0 = blockIdx.y * 8;
    const int n  = blockIdx.z;
    const int h  = h0 + tx;
    const int w  = w0 + ty;

    const float4* tb = reinterpret_cast<const float4*>(g_t2) + (size_t)n * HH * WW;
    const float4* xb = g_xt + (size_t)n * HH * WW;

    const float4 th = __ldg(&tb[h * WW + w]);

    const float yy = -1.f + 2.f * (float)h / (float)(HH - 1);
    const float xx = -1.f + 2.f * (float)w / (float)(WW - 1);

    float acc0 = 0.f, acc1 = 0.f, acc2 = 0.f;

#pragma unroll
    for (int i = 0; i < 3; ++i) {
        const float lyv = (float)(i - 1) * (3.0f / (float)HH);
#pragma unroll
        for (int j = 0; j < 3; ++j) {
            const float lxv = (float)(j - 1) * (3.0f / (float)WW);
            const float gx = yy + th.x * lyv + th.y * lxv;   // grid[...,0] (x coord)
            const float gy = xx + th.z * lyv + th.w * lxv;   // grid[...,1] (y coord)
            const float ix = ((gx + 1.0f) * (float)WW - 1.0f) * 0.5f;
            const float iy = ((gy + 1.0f) * (float)HH - 1.0f) * 0.5f;
            const float ix0 = floorf(ix);
            const float iy0 = floorf(iy);
            const float wx1 = ix - ix0;
            const float wy1 = iy - iy0;
            const float wx0 = 1.0f - wx1;
            const float wy0 = 1.0f - wy1;
            const int xi = (int)ix0;
            const int yi = (int)iy0;

            const float4 v00 = fetch4(xb, xi,     yi);
            const float4 v10 = fetch4(xb, xi + 1, yi);
            const float4 v01 = fetch4(xb, xi,     yi + 1);
            const float4 v11 = fetch4(xb, xi + 1, yi + 1);

            const float w00 = wx0 * wy0, w10 = wx1 * wy0;
            const float w01 = wx0 * wy1, w11 = wx1 * wy1;

            const float vx = v00.x * w00 + v10.x * w10 + v01.x * w01 + v11.x * w11;
            const float vy = v00.y * w00 + v10.y * w10 + v01.y * w01 + v11.y * w11;
            const float vz = v00.z * w00 + v10.z * w10 + v01.z * w01 + v11.z * w11;

            const int k = i * 3 + j;
            acc0 += wsh[0 * 27 + k] * vx + wsh[0 * 27 + 9 + k] * vy + wsh[0 * 27 + 18 + k] * vz;
            acc1 += wsh[1 * 27 + k] * vx + wsh[1 * 27 + 9 + k] * vy + wsh[1 * 27 + 18 + k] * vz;
            acc2 += wsh[2 * 27 + k] * vx + wsh[2 * 27 + 9 + k] * vy + wsh[2 * 27 + 18 + k] * vz;
        }
    }

    so[0][tx][ty] = acc0 + bsh[0];
    so[1][tx][ty] = acc1 + bsh[1];
    so[2][tx][ty] = acc2 + bsh[2];
    __syncthreads();

    for (int e = tid; e < 3 * 32 * 8; e += 256) {
        int oc = e >> 8;
        int r  = (e >> 3) & 31;
        int c  = e & 7;
        out[((size_t)(n * 3 + oc) * HH + h0 + r) * WW + w0 + c] = so[oc][r][c];
    }
}

// ---------------------------------------------------------------------------
extern "C" void kernel_launch(void* const* d_in, const int* in_sizes, int n_in,
                              void* d_out, int out_size)
{
    const float* x  = (const float*)d_in[0];
    const float* w1 = (const float*)d_in[1];
    const float* b1 = (const float*)d_in[2];
    const float* w2 = (const float*)d_in[3];
    const float* b2 = (const float*)d_in[4];
    const float* w3 = (const float*)d_in[5];
    const float* b3 = (const float*)d_in[6];
    const float* w4 = (const float*)d_in[7];
    const float* b4 = (const float*)d_in[8];
    const float* wr = (const float*)d_in[9];
    const float* br = (const float*)d_in[10];
    float* out = (float*)d_out;

    const dim3 cb(32, 8);
    const dim3 cg(WW / 128, HH / 8, NN);     // (5, 60, 4)

    pack_x_kernel<<<(NN * HH * WW + 255) / 256, 256>>>(x);

    conv5_kernel<3, 0, 1, false><<<cg, cb>>>(x, w1, b1);        // x  -> t1
    conv5_kernel<4, 1, 2, false><<<cg, cb>>>(nullptr, w2, b2);  // t1 -> t2
    conv5_kernel<4, 2, 1, false><<<cg, cb>>>(nullptr, w3, b3);  // t2 -> t1
    conv5_kernel<4, 1, 2, true ><<<cg, cb>>>(nullptr, w4, b4);  // t1 -> t2 (theta NHWC4)

    const dim3 sb(32, 8);
    const dim3 sg(HH / 32, WW / 8, NN);      // (15, 80, 4)
    stn_sample_kernel<<<sg, sb>>>(wr, br, out);
}

// round 9
// speedup vs baseline: 1.6492x; 1.0623x over previous
#include <cuda_runtime.h>

#define NN 4
#define HH 480
#define WW 640
#define W4 (WW / 4)

// Scratch (static device arrays; no allocation anywhere)
__device__ float  g_t1[NN * 4 * HH * WW];   // ping (CHW)
__device__ float  g_t2[NN * 4 * HH * WW];   // pong / theta NHWC4
__device__ float4 g_xt[NN * HH * WW];       // x packed NHWC (c=0..2, lane w = 0)

typedef unsigned long long u64;

__device__ __forceinline__ u64 pk(float lo, float hi) {
    u64 r; asm("mov.b64 %0, {%1,%2};" : "=l"(r) : "f"(lo), "f"(hi)); return r;
}
__device__ __forceinline__ void upk(u64 v, float& lo, float& hi) {
    asm("mov.b64 {%0,%1}, %2;" : "=f"(lo), "=f"(hi) : "l"(v));
}
__device__ __forceinline__ u64 fma2(u64 a, u64 b, u64 c) {
    u64 d; asm("fma.rn.f32x2 %0, %1, %2, %3;" : "=l"(d) : "l"(a), "l"(b), "l"(c));
    return d;
}

// ---------------------------------------------------------------------------
// Kernel 0: pack x [N,3,H,W] -> NHWC float4 (4th lane zero)
// ---------------------------------------------------------------------------
__global__ void __launch_bounds__(256) pack_x_kernel(const float* __restrict__ x) {
    int idx = blockIdx.x * 256 + threadIdx.x;
    const int total = NN * HH * WW;
    if (idx >= total) return;
    int n  = idx / (HH * WW);
    int hw = idx - n * (HH * WW);
    const float* xb = x + (size_t)n * 3 * HH * WW + hw;
    float4 v;
    v.x = __ldg(&xb[0]);
    v.y = __ldg(&xb[HH * WW]);
    v.z = __ldg(&xb[2 * HH * WW]);
    v.w = 0.f;
    g_xt[idx] = v;
}

// ---------------------------------------------------------------------------
// 5x5 conv, pad 2, OC=4, CHW. Block 32x8; thread computes 4 ADJACENT px.
// Math packed over oc: acc u64 pairs (oc0,oc1)/(oc2,oc3); pixel broadcast
// into both lanes with one dup-MOV each (8 per row, hoisted); weights stored
// as ulonglong2 -> 1 LDS.128/tap. Per (ic,ky) row: 3 input LDS.128 + 8 MOV +
// 5 weight LDS.128 + 40 FFMA2 (vs 80 scalar FFMA before).
// SRC: 0 = external x, 1 = g_t1, 2 = g_t2.  NHWC_OUT -> float4 theta out.
// ---------------------------------------------------------------------------
template <int IC, int SRC, int DST, bool NHWC_OUT>
__global__ void __launch_bounds__(256) conv5_kernel(
    const float* __restrict__ xin, const float* __restrict__ w,
    const float* __restrict__ b)
{
    __shared__ float      tile[IC][12][136];
    __shared__ ulonglong2 wsh2[IC][5][5];   // [ic][ky][kx] -> (pk(w0,w1), pk(w2,w3))
    __shared__ float4     b4s;

    const int tx  = threadIdx.x;
    const int ty  = threadIdx.y;
    const int tid = ty * 32 + tx;
    const int x0  = blockIdx.x * 128;
    const int y0  = blockIdx.y * 8;
    const int n   = blockIdx.z;

    const float* in = (SRC == 0) ? xin : (SRC == 1) ? g_t1 : g_t2;
    float* out      = (DST == 1) ? g_t1 : g_t2;

    // weights: src layout [OC=4][IC][5][5]
    if (tid < IC * 25) {
        int ic = tid / 25;
        int k  = tid - ic * 25;        // ky*5+kx
        float w0 = __ldg(&w[(0 * IC + ic) * 25 + k]);
        float w1 = __ldg(&w[(1 * IC + ic) * 25 + k]);
        float w2 = __ldg(&w[(2 * IC + ic) * 25 + k]);
        float w3 = __ldg(&w[(3 * IC + ic) * 25 + k]);
        wsh2[ic][k / 5][k % 5] = make_ulonglong2(pk(w0, w1), pk(w2, w3));
    }
    if (tid == 0)
        b4s = make_float4(__ldg(&b[0]), __ldg(&b[1]), __ldg(&b[2]), __ldg(&b[3]));

    // prologue: float4 tile loads. rows y0-2..y0+9, f4-cols x0/4-1 .. x0/4+32
    {
        const float4* in4 = reinterpret_cast<const float4*>(in + (size_t)n * IC * HH * WW);
        const int cbase = (x0 >> 2) - 1;
#pragma unroll 1
        for (int i = tid; i < IC * 12 * 34; i += 256) {
            int ic  = i / (12 * 34);
            int rem = i - ic * (12 * 34);
            int r   = rem / 34;
            int c4  = rem - r * 34;
            int gy  = y0 + r - 2;
            int gx4 = cbase + c4;
            float4 v = make_float4(0.f, 0.f, 0.f, 0.f);
            if ((unsigned)gy < (unsigned)HH && (unsigned)gx4 < (unsigned)W4)
                v = __ldg(&in4[((size_t)ic * HH + gy) * W4 + gx4]);
            *reinterpret_cast<float4*>(&tile[ic][r][4 * c4]) = v;
        }
    }
    __syncthreads();

    // acc pairs: acc01[p] = (oc0,oc1), acc23[p] = (oc2,oc3) for pixel p
    u64 acc01[4], acc23[4];
    {
        const u64 b01 = pk(b4s.x, b4s.y);
        const u64 b23 = pk(b4s.z, b4s.w);
#pragma unroll
        for (int p = 0; p < 4; ++p) { acc01[p] = b01; acc23[p] = b23; }
    }

#pragma unroll 1
    for (int ic = 0; ic < IC; ++ic) {
#pragma unroll
        for (int ky = 0; ky < 5; ++ky) {
            const float4* rowp =
                reinterpret_cast<const float4*>(&tile[ic][ty + ky][4 * tx]);
            const float4 a0 = rowp[0];
            const float4 a1 = rowp[1];
            const float4 a2 = rowp[2];
            const float v[12] = {a0.x, a0.y, a0.z, a0.w,
                                 a1.x, a1.y, a1.z, a1.w,
                                 a2.x, a2.y, a2.z, a2.w};
            // duplicate pixels v[2..9] into both f32x2 lanes (1 MOV each)
            u64 d[8];
#pragma unroll
            for (int j = 0; j < 8; ++j) d[j] = pk(v[2 + j], v[2 + j]);
#pragma unroll
            for (int kx = 0; kx < 5; ++kx) {
                const ulonglong2 wp = wsh2[ic][ky][kx];
#pragma unroll
                for (int p = 0; p < 4; ++p) {
                    acc01[p] = fma2(d[p + kx], wp.x, acc01[p]);
                    acc23[p] = fma2(d[p + kx], wp.y, acc23[p]);
                }
            }
        }
    }

    const int y  = y0 + ty;
    const int xb = x0 + 4 * tx;

    float o[4][4];   // [oc][px]
#pragma unroll
    for (int p = 0; p < 4; ++p) {
        upk(acc01[p], o[0][p], o[1][p]);
        upk(acc23[p], o[2][p], o[3][p]);
    }

    if (NHWC_OUT) {
        float4* o4 = reinterpret_cast<float4*>(out) + (size_t)n * HH * WW + y * WW + xb;
#pragma unroll
        for (int p = 0; p < 4; ++p)
            o4[p] = make_float4(o[0][p], o[1][p], o[2][p], o[3][p]);
    } else {
#pragma unroll
        for (int oc = 0; oc < 4; ++oc) {
            float4* op = reinterpret_cast<float4*>(
                out + ((size_t)(n * 4 + oc) * HH + y) * WW + xb);
            *op = make_float4(o[oc][0], o[oc][1], o[oc][2], o[oc][3]);
        }
    }
}

// ---------------------------------------------------------------------------
// Fused: grid build + bilinear grid_sample + stride-3 3x3 conv epilogue.
// theta in NHWC float4 (g_t2). x in NHWC float4 (g_xt).
// Thread map: tx -> h (gathers coalesced along x columns), ty -> w.
// ---------------------------------------------------------------------------
__device__ __forceinline__ float4 fetch4(const float4* __restrict__ b, int x, int y) {
    if ((unsigned)x < (unsigned)WW && (unsigned)y < (unsigned)HH)
        return __ldg(&b[y * WW + x]);
    return make_float4(0.f, 0.f, 0.f, 0.f);
}

__global__ void __launch_bounds__(256) stn_sample_kernel(
    const float* __restrict__ wr, const float* __restrict__ br,
    float* __restrict__ out)
{
    __shared__ float wsh[81];
    __shared__ float bsh[3];
    __shared__ float so[3][32][9];

    const int tx  = threadIdx.x;
    const int ty  = threadIdx.y;
    const int tid = ty * 32 + tx;
    if (tid < 81) wsh[tid] = __ldg(&wr[tid]);
    if (tid < 3)  bsh[tid] = __ldg(&br[tid]);
    __syncthreads();

    const int h0 = blockIdx.x * 32;
    const int w0 = blockIdx.y * 8;
    const int n  = blockIdx.z;
    const int h  = h0 + tx;
    const int w  = w0 + ty;

    const float4* tb = reinterpret_cast<const float4*>(g_t2) + (size_t)n * HH * WW;
    const float4* xb = g_xt + (size_t)n * HH * WW;

    const float4 th = __ldg(&tb[h * WW + w]);

    const float yy = -1.f + 2.f * (float)h / (float)(HH - 1);
    const float xx = -1.f + 2.f * (float)w / (float)(WW - 1);

    float acc0 = 0.f, acc1 = 0.f, acc2 = 0.f;

#pragma unroll
    for (int i = 0; i < 3; ++i) {
        const float lyv = (float)(i - 1) * (3.0f / (float)HH);
#pragma unroll
        for (int j = 0; j < 3; ++j) {
            const float lxv = (float)(j - 1) * (3.0f / (float)WW);
            const float gx = yy + th.x * lyv + th.y * lxv;   // grid[...,0] (x coord)
            const float gy = xx + th.z * lyv + th.w * lxv;   // grid[...,1] (y coord)
            const float ix = ((gx + 1.0f) * (float)WW - 1.0f) * 0.5f;
            const float iy = ((gy + 1.0f) * (float)HH - 1.0f) * 0.5f;
            const float ix0 = floorf(ix);
            const float iy0 = floorf(iy);
            const float wx1 = ix - ix0;
            const float wy1 = iy - iy0;
            const float wx0 = 1.0f - wx1;
            const float wy0 = 1.0f - wy1;
            const int xi = (int)ix0;
            const int yi = (int)iy0;

            const float4 v00 = fetch4(xb, xi,     yi);
            const float4 v10 = fetch4(xb, xi + 1, yi);
            const float4 v01 = fetch4(xb, xi,     yi + 1);
            const float4 v11 = fetch4(xb, xi + 1, yi + 1);

            const float w00 = wx0 * wy0, w10 = wx1 * wy0;
            const float w01 = wx0 * wy1, w11 = wx1 * wy1;

            const float vx = v00.x * w00 + v10.x * w10 + v01.x * w01 + v11.x * w11;
            const float vy = v00.y * w00 + v10.y * w10 + v01.y * w01 + v11.y * w11;
            const float vz = v00.z * w00 + v10.z * w10 + v01.z * w01 + v11.z * w11;

            const int k = i * 3 + j;
            acc0 += wsh[0 * 27 + k] * vx + wsh[0 * 27 + 9 + k] * vy + wsh[0 * 27 + 18 + k] * vz;
            acc1 += wsh[1 * 27 + k] * vx + wsh[1 * 27 + 9 + k] * vy + wsh[1 * 27 + 18 + k] * vz;
            acc2 += wsh[2 * 27 + k] * vx + wsh[2 * 27 + 9 + k] * vy + wsh[2 * 27 + 18 + k] * vz;
        }
    }

    so[0][tx][ty] = acc0 + bsh[0];
    so[1][tx][ty] = acc1 + bsh[1];
    so[2][tx][ty] = acc2 + bsh[2];
    __syncthreads();

    for (int e = tid; e < 3 * 32 * 8; e += 256) {
        int oc = e >> 8;
        int r  = (e >> 3) & 31;
        int c  = e & 7;
        out[((size_t)(n * 3 + oc) * HH + h0 + r) * WW + w0 + c] = so[oc][r][c];
    }
}

// ---------------------------------------------------------------------------
extern "C" void kernel_launch(void* const* d_in, const int* in_sizes, int n_in,
                              void* d_out, int out_size)
{
    const float* x  = (const float*)d_in[0];
    const float* w1 = (const float*)d_in[1];
    const float* b1 = (const float*)d_in[2];
    const float* w2 = (const float*)d_in[3];
    const float* b2 = (const float*)d_in[4];
    const float* w3 = (const float*)d_in[5];
    const float* b3 = (const float*)d_in[6];
    const float* w4 = (const float*)d_in[7];
    const float* b4 = (const float*)d_in[8];
    const float* wr = (const float*)d_in[9];
    const float* br = (const float*)d_in[10];
    float* out = (float*)d_out;

    const dim3 cb(32, 8);
    const dim3 cg(WW / 128, HH / 8, NN);     // (5, 60, 4)

    pack_x_kernel<<<(NN * HH * WW + 255) / 256, 256>>>(x);

    conv5_kernel<3, 0, 1, false><<<cg, cb>>>(x, w1, b1);        // x  -> t1
    conv5_kernel<4, 1, 2, false><<<cg, cb>>>(nullptr, w2, b2);  // t1 -> t2
    conv5_kernel<4, 2, 1, false><<<cg, cb>>>(nullptr, w3, b3);  // t2 -> t1
    conv5_kernel<4, 1, 2, true ><<<cg, cb>>>(nullptr, w4, b4);  // t1 -> t2 (theta NHWC4)

    const dim3 sb(32, 8);
    const dim3 sg(HH / 32, WW / 8, NN);      // (15, 80, 4)
    stn_sample_kernel<<<sg, sb>>>(wr, br, out);
}

// round 10
// speedup vs baseline: 1.7836x; 1.0815x over previous
#include <cuda_runtime.h>

#define NN 4
#define HH 480
#define WW 640
#define W4 (WW / 4)

// Scratch (static device arrays; no allocation anywhere)
__device__ float  g_t1[NN * 4 * HH * WW];   // ping (CHW)
__device__ float  g_t2[NN * 4 * HH * WW];   // pong / theta NHWC4
__device__ float4 g_xt[NN * HH * WW];       // x packed NHWC (c=0..2, lane w = 0)

typedef unsigned long long u64;

__device__ __forceinline__ u64 pk(float lo, float hi) {
    u64 r; asm("mov.b64 %0, {%1,%2};" : "=l"(r) : "f"(lo), "f"(hi)); return r;
}
__device__ __forceinline__ void upk(u64 v, float& lo, float& hi) {
    asm("mov.b64 {%0,%1}, %2;" : "=f"(lo), "=f"(hi) : "l"(v));
}
__device__ __forceinline__ u64 fma2(u64 a, u64 b, u64 c) {
    u64 d; asm("fma.rn.f32x2 %0, %1, %2, %3;" : "=l"(d) : "l"(a), "l"(b), "l"(c));
    return d;
}

// ---------------------------------------------------------------------------
// Kernel 0: pack x [N,3,H,W] -> NHWC float4 (4th lane zero)
// ---------------------------------------------------------------------------
__global__ void __launch_bounds__(256) pack_x_kernel(const float* __restrict__ x) {
    int idx = blockIdx.x * 256 + threadIdx.x;
    const int total = NN * HH * WW;
    if (idx >= total) return;
    int n  = idx / (HH * WW);
    int hw = idx - n * (HH * WW);
    const float* xb = x + (size_t)n * 3 * HH * WW + hw;
    float4 v;
    v.x = __ldg(&xb[0]);
    v.y = __ldg(&xb[HH * WW]);
    v.z = __ldg(&xb[2 * HH * WW]);
    v.w = 0.f;
    g_xt[idx] = v;
}

// ---------------------------------------------------------------------------
// 5x5 conv, pad 2, OC=4, CHW. Block 32x8; thread computes 4 ADJACENT px.
// Math packed over oc (FFMA2): acc u64 pairs (oc0,oc1)/(oc2,oc3).
// SRC: 0 = external x, 1 = g_t1, 2 = g_t2.  NHWC_OUT -> float4 theta out.
// ---------------------------------------------------------------------------
template <int IC, int SRC, int DST, bool NHWC_OUT>
__global__ void __launch_bounds__(256) conv5_kernel(
    const float* __restrict__ xin, const float* __restrict__ w,
    const float* __restrict__ b)
{
    __shared__ float      tile[IC][12][136];
    __shared__ ulonglong2 wsh2[IC][5][5];   // [ic][ky][kx] -> (pk(w0,w1), pk(w2,w3))
    __shared__ float4     b4s;

    const int tx  = threadIdx.x;
    const int ty  = threadIdx.y;
    const int tid = ty * 32 + tx;
    const int x0  = blockIdx.x * 128;
    const int y0  = blockIdx.y * 8;
    const int n   = blockIdx.z;

    const float* in = (SRC == 0) ? xin : (SRC == 1) ? g_t1 : g_t2;
    float* out      = (DST == 1) ? g_t1 : g_t2;

    // weights: src layout [OC=4][IC][5][5]
    if (tid < IC * 25) {
        int ic = tid / 25;
        int k  = tid - ic * 25;        // ky*5+kx
        float w0 = __ldg(&w[(0 * IC + ic) * 25 + k]);
        float w1 = __ldg(&w[(1 * IC + ic) * 25 + k]);
        float w2 = __ldg(&w[(2 * IC + ic) * 25 + k]);
        float w3 = __ldg(&w[(3 * IC + ic) * 25 + k]);
        wsh2[ic][k / 5][k % 5] = make_ulonglong2(pk(w0, w1), pk(w2, w3));
    }
    if (tid == 0)
        b4s = make_float4(__ldg(&b[0]), __ldg(&b[1]), __ldg(&b[2]), __ldg(&b[3]));

    // prologue: float4 tile loads. rows y0-2..y0+9, f4-cols x0/4-1 .. x0/4+32
    {
        const float4* in4 = reinterpret_cast<const float4*>(in + (size_t)n * IC * HH * WW);
        const int cbase = (x0 >> 2) - 1;
#pragma unroll 1
        for (int i = tid; i < IC * 12 * 34; i += 256) {
            int ic  = i / (12 * 34);
            int rem = i - ic * (12 * 34);
            int r   = rem / 34;
            int c4  = rem - r * 34;
            int gy  = y0 + r - 2;
            int gx4 = cbase + c4;
            float4 v = make_float4(0.f, 0.f, 0.f, 0.f);
            if ((unsigned)gy < (unsigned)HH && (unsigned)gx4 < (unsigned)W4)
                v = __ldg(&in4[((size_t)ic * HH + gy) * W4 + gx4]);
            *reinterpret_cast<float4*>(&tile[ic][r][4 * c4]) = v;
        }
    }
    __syncthreads();

    // acc pairs: acc01[p] = (oc0,oc1), acc23[p] = (oc2,oc3) for pixel p
    u64 acc01[4], acc23[4];
    {
        const u64 b01 = pk(b4s.x, b4s.y);
        const u64 b23 = pk(b4s.z, b4s.w);
#pragma unroll
        for (int p = 0; p < 4; ++p) { acc01[p] = b01; acc23[p] = b23; }
    }

#pragma unroll 1
    for (int ic = 0; ic < IC; ++ic) {
#pragma unroll
        for (int ky = 0; ky < 5; ++ky) {
            const float4* rowp =
                reinterpret_cast<const float4*>(&tile[ic][ty + ky][4 * tx]);
            const float4 a0 = rowp[0];
            const float4 a1 = rowp[1];
            const float4 a2 = rowp[2];
            const float v[12] = {a0.x, a0.y, a0.z, a0.w,
                                 a1.x, a1.y, a1.z, a1.w,
                                 a2.x, a2.y, a2.z, a2.w};
            u64 d[8];
#pragma unroll
            for (int j = 0; j < 8; ++j) d[j] = pk(v[2 + j], v[2 + j]);
#pragma unroll
            for (int kx = 0; kx < 5; ++kx) {
                const ulonglong2 wp = wsh2[ic][ky][kx];
#pragma unroll
                for (int p = 0; p < 4; ++p) {
                    acc01[p] = fma2(d[p + kx], wp.x, acc01[p]);
                    acc23[p] = fma2(d[p + kx], wp.y, acc23[p]);
                }
            }
        }
    }

    const int y  = y0 + ty;
    const int xb = x0 + 4 * tx;

    float o[4][4];   // [oc][px]
#pragma unroll
    for (int p = 0; p < 4; ++p) {
        upk(acc01[p], o[0][p], o[1][p]);
        upk(acc23[p], o[2][p], o[3][p]);
    }

    if (NHWC_OUT) {
        float4* o4 = reinterpret_cast<float4*>(out) + (size_t)n * HH * WW + y * WW + xb;
#pragma unroll
        for (int p = 0; p < 4; ++p)
            o4[p] = make_float4(o[0][p], o[1][p], o[2][p], o[3][p]);
    } else {
#pragma unroll
        for (int oc = 0; oc < 4; ++oc) {
            float4* op = reinterpret_cast<float4*>(
                out + ((size_t)(n * 4 + oc) * HH + y) * WW + xb);
            *op = make_float4(o[oc][0], o[oc][1], o[oc][2], o[oc][3]);
        }
    }
}

// ---------------------------------------------------------------------------
// Fused: grid build + bilinear grid_sample + stride-3 3x3 conv epilogue.
// theta in NHWC float4 (g_t2). x in NHWC float4 (g_xt).
// Thread map: tx -> h, ty -> w.
// Corner cache: the 9 subsamples of one output pixel perturb the sample
// point by <<1 px, so their bilinear corner indices (xi,yi) almost always
// coincide -> fetch the 4 corners once and refetch only when (xi,yi) changes
// (bitwise-identical result: same indices imply same corner values).
// ---------------------------------------------------------------------------
__device__ __forceinline__ float4 fetch4(const float4* __restrict__ b, int x, int y) {
    if ((unsigned)x < (unsigned)WW && (unsigned)y < (unsigned)HH)
        return __ldg(&b[y * WW + x]);
    return make_float4(0.f, 0.f, 0.f, 0.f);
}

__global__ void __launch_bounds__(256) stn_sample_kernel(
    const float* __restrict__ wr, const float* __restrict__ br,
    float* __restrict__ out)
{
    __shared__ float wsh[81];
    __shared__ float bsh[3];
    __shared__ float so[3][32][9];

    const int tx  = threadIdx.x;
    const int ty  = threadIdx.y;
    const int tid = ty * 32 + tx;
    if (tid < 81) wsh[tid] = __ldg(&wr[tid]);
    if (tid < 3)  bsh[tid] = __ldg(&br[tid]);
    __syncthreads();

    const int h0 = blockIdx.x * 32;
    const int w0 = blockIdx.y * 8;
    const int n  = blockIdx.z;
    const int h  = h0 + tx;
    const int w  = w0 + ty;

    const float4* tb = reinterpret_cast<const float4*>(g_t2) + (size_t)n * HH * WW;
    const float4* xb = g_xt + (size_t)n * HH * WW;

    const float4 th = __ldg(&tb[h * WW + w]);

    const float yy = -1.f + 2.f * (float)h / (float)(HH - 1);
    const float xx = -1.f + 2.f * (float)w / (float)(WW - 1);

    float acc0 = 0.f, acc1 = 0.f, acc2 = 0.f;

    // corner cache
    int cxi = (int)0x80000000, cyi = (int)0x80000000;
    float4 c00, c10, c01, c11;
    c00 = c10 = c01 = c11 = make_float4(0.f, 0.f, 0.f, 0.f);

#pragma unroll
    for (int i = 0; i < 3; ++i) {
        const float lyv = (float)(i - 1) * (3.0f / (float)HH);
#pragma unroll
        for (int j = 0; j < 3; ++j) {
            const float lxv = (float)(j - 1) * (3.0f / (float)WW);
            const float gx = yy + th.x * lyv + th.y * lxv;   // grid[...,0] (x coord)
            const float gy = xx + th.z * lyv + th.w * lxv;   // grid[...,1] (y coord)
            const float ix = ((gx + 1.0f) * (float)WW - 1.0f) * 0.5f;
            const float iy = ((gy + 1.0f) * (float)HH - 1.0f) * 0.5f;
            const float ix0 = floorf(ix);
            const float iy0 = floorf(iy);
            const float wx1 = ix - ix0;
            const float wy1 = iy - iy0;
            const float wx0 = 1.0f - wx1;
            const float wy0 = 1.0f - wy1;
            const int xi = (int)ix0;
            const int yi = (int)iy0;

            if (xi != cxi || yi != cyi) {
                c00 = fetch4(xb, xi,     yi);
                c10 = fetch4(xb, xi + 1, yi);
                c01 = fetch4(xb, xi,     yi + 1);
                c11 = fetch4(xb, xi + 1, yi + 1);
                cxi = xi; cyi = yi;
            }

            const float w00 = wx0 * wy0, w10 = wx1 * wy0;
            const float w01 = wx0 * wy1, w11 = wx1 * wy1;

            const float vx = c00.x * w00 + c10.x * w10 + c01.x * w01 + c11.x * w11;
            const float vy = c00.y * w00 + c10.y * w10 + c01.y * w01 + c11.y * w11;
            const float vz = c00.z * w00 + c10.z * w10 + c01.z * w01 + c11.z * w11;

            const int k = i * 3 + j;
            acc0 += wsh[0 * 27 + k] * vx + wsh[0 * 27 + 9 + k] * vy + wsh[0 * 27 + 18 + k] * vz;
            acc1 += wsh[1 * 27 + k] * vx + wsh[1 * 27 + 9 + k] * vy + wsh[1 * 27 + 18 + k] * vz;
            acc2 += wsh[2 * 27 + k] * vx + wsh[2 * 27 + 9 + k] * vy + wsh[2 * 27 + 18 + k] * vz;
        }
    }

    so[0][tx][ty] = acc0 + bsh[0];
    so[1][tx][ty] = acc1 + bsh[1];
    so[2][tx][ty] = acc2 + bsh[2];
    __syncthreads();

    for (int e = tid; e < 3 * 32 * 8; e += 256) {
        int oc = e >> 8;
        int r  = (e >> 3) & 31;
        int c  = e & 7;
        out[((size_t)(n * 3 + oc) * HH + h0 + r) * WW + w0 + c] = so[oc][r][c];
    }
}

// ---------------------------------------------------------------------------
extern "C" void kernel_launch(void* const* d_in, const int* in_sizes, int n_in,
                              void* d_out, int out_size)
{
    const float* x  = (const float*)d_in[0];
    const float* w1 = (const float*)d_in[1];
    const float* b1 = (const float*)d_in[2];
    const float* w2 = (const float*)d_in[3];
    const float* b2 = (const float*)d_in[4];
    const float* w3 = (const float*)d_in[5];
    const float* b3 = (const float*)d_in[6];
    const float* w4 = (const float*)d_in[7];
    const float* b4 = (const float*)d_in[8];
    const float* wr = (const float*)d_in[9];
    const float* br = (const float*)d_in[10];
    float* out = (float*)d_out;

    const dim3 cb(32, 8);
    const dim3 cg(WW / 128, HH / 8, NN);     // (5, 60, 4)

    pack_x_kernel<<<(NN * HH * WW + 255) / 256, 256>>>(x);

    conv5_kernel<3, 0, 1, false><<<cg, cb>>>(x, w1, b1);        // x  -> t1
    conv5_kernel<4, 1, 2, false><<<cg, cb>>>(nullptr, w2, b2);  // t1 -> t2
    conv5_kernel<4, 2, 1, false><<<cg, cb>>>(nullptr, w3, b3);  // t2 -> t1
    conv5_kernel<4, 1, 2, true ><<<cg, cb>>>(nullptr, w4, b4);  // t1 -> t2 (theta NHWC4)

    const dim3 sb(32, 8);
    const dim3 sg(HH / 32, WW / 8, NN);      // (15, 80, 4)
    stn_sample_kernel<<<sg, sb>>>(wr, br, out);
}